// round 15
// baseline (speedup 1.0000x reference)
#include <cuda_runtime.h>

#define BB 32
#define TT 1024
#define NN 128
#define RBLK 4
#define ROWS 32
#define THREADS 128
#define TR 4
#define TC 8
#define LANES 16
#define CHUNK 32
#define NCHUNK (TT / CHUNK)

// pbuf in float4 units: [buf2][step][q][lane]; q stride 17, step stride 137
#define PB_Q    17
#define PB_STEP 137
#define PB_HALF (CHUNK * PB_STEP)

// smem layout (float offsets)
#define SM_XS     0                                  // 3 x 4096 floats
#define SM_PBUF   (3 * CHUNK * NN)                   // 12288
#define SM_SCOEF  (SM_PBUF + 2 * PB_HALF * 4)        // pbuf doubled: +35072
#define SM_CSCALE (SM_SCOEF + TT + 4)
#define SM_CFOLD  (SM_CSCALE + TT)
#define SM_APOW   (SM_CFOLD + NCHUNK)
#define SM_APOWI  (SM_APOW + CHUNK + 1)
#define SM_MBITS  (SM_APOWI + CHUNK + 1)
#define SM_MBAR   (((SM_MBITS + NCHUNK) + 3) & ~3)   // 16B aligned, 6 x u64
#define SM_FLOATS (SM_MBAR + 12)
#define SM_BYTES  (SM_FLOATS * 4)                    // ~198 KB

typedef unsigned long long u64;

// ---------- packed f32x2 helpers ----------
__device__ __forceinline__ u64 pack2(float lo, float hi) {
    u64 r; asm("mov.b64 %0, {%1, %2};" : "=l"(r) : "f"(lo), "f"(hi)); return r;
}
__device__ __forceinline__ void unpack2(u64 v, float& lo, float& hi) {
    asm("mov.b64 {%0, %1}, %2;" : "=f"(lo), "=f"(hi) : "l"(v));
}
__device__ __forceinline__ u64 fma2(u64 a, u64 b, u64 c) {
    u64 d; asm("fma.rn.f32x2 %0, %1, %2, %3;" : "=l"(d) : "l"(a), "l"(b), "l"(c)); return d;
}
__device__ __forceinline__ u64 mul2(u64 a, u64 b) {
    u64 d; asm("mul.rn.f32x2 %0, %1, %2;" : "=l"(d) : "l"(a), "l"(b)); return d;
}
__device__ __forceinline__ u64 add2(u64 a, u64 b) {
    u64 d; asm("add.rn.f32x2 %0, %1, %2;" : "=l"(d) : "l"(a), "l"(b)); return d;
}

// ---------- mbarrier helpers ----------
__device__ __forceinline__ unsigned smem_u32(const void* p) {
    return (unsigned)__cvta_generic_to_shared(p);
}
__device__ __forceinline__ void mbar_init(unsigned a, unsigned cnt) {
    asm volatile("mbarrier.init.shared.b64 [%0], %1;" :: "r"(a), "r"(cnt) : "memory");
}
__device__ __forceinline__ void mbar_arrive(unsigned a) {
    asm volatile("mbarrier.arrive.shared.b64 _, [%0];" :: "r"(a) : "memory");
}
__device__ __forceinline__ void mbar_wait(unsigned a, unsigned parity) {
    unsigned done;
    do {
        asm volatile(
            "{\n\t.reg .pred p;\n\t"
            "mbarrier.try_wait.parity.acquire.cta.shared::cta.b64 p, [%1], %2, 0x989680;\n\t"
            "selp.b32 %0, 1, 0, p;\n\t}"
            : "=r"(done) : "r"(a), "r"(parity) : "memory");
    } while (!done);
}
// .noinc: completion arrive counts against the INIT count (proven in R12).
__device__ __forceinline__ void cpasync_mbar_arrive(unsigned a) {
    asm volatile("cp.async.mbarrier.arrive.noinc.shared::cta.b64 [%0];" :: "r"(a) : "memory");
}

// ---------- cp.async ----------
__device__ __forceinline__ void cpasync16(void* s, const void* g) {
    unsigned saddr = smem_u32(s);
    asm volatile("cp.async.cg.shared.global [%0], [%1], 16;" :: "r"(saddr), "l"(g));
}
__device__ __forceinline__ void load_chunk(float* dst, const float* src, int tid) {
    #pragma unroll
    for (int i = 0; i < 8; i++) {
        int off = (tid + i * THREADS) * 4;
        cpasync16(dst + off, src + off);
    }
}

__global__ __launch_bounds__(THREADS, 1)
void bdh_scan_kernel(const float* __restrict__ x,
                     const float* __restrict__ w_init,
                     const float* __restrict__ alpha_p,
                     const float* __restrict__ eta_p,
                     const int*   __restrict__ mask,
                     float* __restrict__ w_out,
                     float* __restrict__ y_out)
{
    extern __shared__ float smem[];
    float*    xs     = smem + SM_XS;
    float4*   pbuf   = reinterpret_cast<float4*>(smem + SM_PBUF);
    float*    scoef  = smem + SM_SCOEF;
    float*    cscale = smem + SM_CSCALE;
    float*    cfold  = smem + SM_CFOLD;
    float*    apow   = smem + SM_APOW;
    float*    apowi  = smem + SM_APOWI;
    unsigned* mbits  = (unsigned*)(smem + SM_MBITS);
    const unsigned mb_base = smem_u32(smem + SM_MBAR);
    // full[i] at mb_base + i*8, empty[i] at mb_base + 24 + i*8

    const int b    = blockIdx.x;
    const int rb   = blockIdx.y;
    const int tid  = threadIdx.x;
    const int q    = tid / LANES;          // 0..7 row-group
    const int lane = tid % LANES;
    const int w    = tid >> 5;             // warp 0..3
    const int l32  = tid & 31;
    const int r0l  = q * TR;
    const int r0   = rb * ROWS + r0l;
    const int cseg = lane * TC;

    const float alpha = alpha_p[0];
    const float eta   = eta_p[0];
    const float inva  = 1.0f / alpha;

    const float* xb = x + (size_t)b * TT * NN;
    float* yb = y_out + (size_t)b * TT * NN;

    // ---- init mbarriers ----
    if (tid == 0) {
        #pragma unroll
        for (int i = 0; i < 3; i++) {
            mbar_init(mb_base + i * 8, THREADS);        // full
            mbar_init(mb_base + 24 + i * 8, THREADS);   // empty
        }
    }
    __syncthreads();
    mbar_arrive(mb_base + 24);
    mbar_arrive(mb_base + 32);
    mbar_arrive(mb_base + 40);

    // ---- prologue fills: buffers 0, 1 ----
    mbar_wait(mb_base + 24, 0);
    load_chunk(xs, xb, tid);
    cpasync_mbar_arrive(mb_base + 0);
    mbar_wait(mb_base + 32, 0);
    load_chunk(xs + CHUNK * NN, xb + CHUNK * NN, tid);
    cpasync_mbar_arrive(mb_base + 8);

    // ---- W tile: 4 rows x 8 cols = 16 packed f32x2 ----
    u64 w2[TR][4];
    {
        const float* wb = w_init + (size_t)b * NN * NN + (size_t)r0 * NN + cseg;
        #pragma unroll
        for (int i = 0; i < TR; i++) {
            const ulonglong2* ws = reinterpret_cast<const ulonglong2*>(wb + i * NN);
            ulonglong2 v0 = ws[0], v1 = ws[1];
            w2[i][0] = v0.x; w2[i][1] = v0.y; w2[i][2] = v1.x; w2[i][3] = v1.y;
        }
    }

    // ---- setup: mask bits + power tables ----
    for (int ckk = w; ckk < NCHUNK; ckk += 4) {
        int m = mask[(size_t)b * TT + ckk * 32 + l32];
        unsigned bits = __ballot_sync(0xffffffffu, m != 0);
        if (l32 == 0) mbits[ckk] = bits;
    }
    if (tid == 0) {
        float p = 1.0f, pi = 1.0f;
        #pragma unroll
        for (int k = 0; k <= CHUNK; k++) {
            apow[k] = p;  apowi[k] = pi;
            p *= alpha;   pi *= inva;
        }
    }
    __syncthreads();
    #pragma unroll
    for (int k = 0; k < 8; k++) {
        const int e = tid + k * THREADS;      // 0..1023
        const int ckk = e >> 5, tl = e & 31;
        const unsigned mb = mbits[ckk];
        const int cnt = __popc(mb & ((1u << tl) - 1u));
        cscale[e] = apow[cnt];
        scoef[e]  = ((mb >> tl) & 1u) ? (eta * apowi[cnt + 1]) : 0.0f;
    }
    if (tid < NCHUNK) cfold[tid] = apow[__popc(mbits[tid])];
    if (tid < 4) scoef[TT + tid] = 0.0f;      // sc4 over-read pad
    __syncthreads();   // tables visible; last block-wide sync

    float4* pbst0 = pbuf + q * PB_Q + lane;   // partial slot, buffer 0
    // fused-reduce base (per chunk: + prev-buffer offset)
    const int rro = l32 * PB_STEP + (2 * w) * PB_Q;

    for (int ck = 0; ck < NCHUNK; ck++) {
        // prefetch ck+2 into buffer (ck+2)%3 once drained by all warps
        const int nk = ck + 2;
        if (nk < NCHUNK) {
            const int nb = nk % 3;
            mbar_wait(mb_base + 24 + nb * 8, (nk / 3) & 1);
            load_chunk(xs + nb * (CHUNK * NN), xb + (size_t)nk * CHUNK * NN, tid);
            cpasync_mbar_arrive(mb_base + nb * 8);
        }

        // wait this chunk's x (warp-independent)
        const int cb = ck % 3;
        mbar_wait(mb_base + cb * 8, (ck / 3) & 1);

        const float* xch = xs + cb * (CHUNK * NN);
        const float4* scp4 = reinterpret_cast<const float4*>(scoef + ck * CHUNK);
        float4* pbst = pbst0 + (ck & 1) * PB_HALF;              // write buffer
        const float4* rp = pbuf + ((ck ^ 1) & 1) * PB_HALF + rro; // prev buffer
        // y scale for this warp's fused outputs (step s = l32 of chunk ck-1)
        const float scy = cscale[((ck > 0 ? ck : 1) - 1) * CHUNK + l32];
        const u64 scy2 = pack2(scy, scy);
        float* ybprev = yb + (size_t)((ck - 1) * CHUNK + l32) * NN + rb * ROWS;

        // ---- software-pipelined, branch-free step loop + fused reduce ----
        ulonglong2 va = reinterpret_cast<const ulonglong2*>(xch + cseg)[0];
        ulonglong2 vb = reinterpret_cast<const ulonglong2*>(xch + cseg)[1];
        float4 xr = *reinterpret_cast<const float4*>(xch + rb * ROWS + r0l);
        float4 sc4 = scp4[0];
        u64 accx = 0, accy = 0;

        #pragma unroll 16
        for (int tl = 0; tl < CHUNK; tl++) {
            const u64 xv0 = va.x, xv1 = va.y, xv2 = vb.x, xv3 = vb.y;
            const float4 xrc = xr;
            const float scc = (tl & 3) == 0 ? sc4.x :
                              (tl & 3) == 1 ? sc4.y :
                              (tl & 3) == 2 ? sc4.z : sc4.w;

            // ---- fused reduce of chunk ck-1: one slot per step ----
            {
                const int o = tl >> 4;        // output 0/1 (row-quad 2w / 2w+1)
                const int j = tl & 15;        // lane slot
                ulonglong2 v = *reinterpret_cast<const ulonglong2*>(
                    rp + o * PB_Q + j);
                if (j == 0) { accx = v.x; accy = v.y; }
                else        { accx = add2(accx, v.x); accy = add2(accy, v.y); }
                if (j == 15 && ck > 0) {      // finalize + store y
                    ulonglong2 out;
                    out.x = mul2(accx, scy2);
                    out.y = mul2(accy, scy2);
                    *reinterpret_cast<ulonglong2*>(
                        ybprev + (2 * w + o) * 4) = out;
                }
            }

            // prefetch next step (tl==31 over-reads pads; discarded)
            const float* xpn = xch + (tl + 1) * NN;
            va = reinterpret_cast<const ulonglong2*>(xpn + cseg)[0];
            vb = reinterpret_cast<const ulonglong2*>(xpn + cseg)[1];
            xr = *reinterpret_cast<const float4*>(xpn + rb * ROWS + r0l);
            if ((tl & 3) == 3) sc4 = scp4[(tl >> 2) + 1];

            // 4 independent dot chains (pre-update W)
            float p[TR];
            #pragma unroll
            for (int i = 0; i < TR; i++) {
                u64 a = mul2(w2[i][0], xv0);
                a = fma2(w2[i][1], xv1, a);
                a = fma2(w2[i][2], xv2, a);
                a = fma2(w2[i][3], xv3, a);
                float lo, hi; unpack2(a, lo, hi);
                p[i] = lo + hi;
            }
            pbst[tl * PB_STEP] = make_float4(p[0], p[1], p[2], p[3]);

            // branch-free masked update (scc == 0 on unmasked steps)
            const float g0f = scc * xrc.x, g1f = scc * xrc.y;
            const float g2f = scc * xrc.z, g3f = scc * xrc.w;
            const u64 g0 = pack2(g0f, g0f);
            const u64 g1 = pack2(g1f, g1f);
            const u64 g2 = pack2(g2f, g2f);
            const u64 g3 = pack2(g3f, g3f);
            w2[0][0] = fma2(g0, xv0, w2[0][0]);
            w2[0][1] = fma2(g0, xv1, w2[0][1]);
            w2[0][2] = fma2(g0, xv2, w2[0][2]);
            w2[0][3] = fma2(g0, xv3, w2[0][3]);
            w2[1][0] = fma2(g1, xv0, w2[1][0]);
            w2[1][1] = fma2(g1, xv1, w2[1][1]);
            w2[1][2] = fma2(g1, xv2, w2[1][2]);
            w2[1][3] = fma2(g1, xv3, w2[1][3]);
            w2[2][0] = fma2(g2, xv0, w2[2][0]);
            w2[2][1] = fma2(g2, xv1, w2[2][1]);
            w2[2][2] = fma2(g2, xv2, w2[2][2]);
            w2[2][3] = fma2(g2, xv3, w2[2][3]);
            w2[3][0] = fma2(g3, xv0, w2[3][0]);
            w2[3][1] = fma2(g3, xv1, w2[3][1]);
            w2[3][2] = fma2(g3, xv2, w2[3][2]);
            w2[3][3] = fma2(g3, xv3, w2[3][3]);
        }

        // unconditional decay fold
        {
            const float cf = cfold[ck];
            const u64 c2 = pack2(cf, cf);
            #pragma unroll
            for (int i = 0; i < TR; i++)
                #pragma unroll
                for (int k = 0; k < 4; k++) w2[i][k] = mul2(w2[i][k], c2);
        }

        // done reading xs[cb] -> release (128 arrivals total)
        mbar_arrive(mb_base + 24 + cb * 8);

        // order: pbuf stores(ck) before fused reads in chunk ck+1 (same warp)
        __syncwarp();
    }

    // ---- epilogue: reduce final chunk (31) from pbuf[1] ----
    {
        const float4* rp = pbuf + ((NCHUNK - 1) & 1) * PB_HALF + rro;
        const float scy = cscale[(NCHUNK - 1) * CHUNK + l32];
        const u64 scy2 = pack2(scy, scy);
        float* ybl = yb + (size_t)((NCHUNK - 1) * CHUNK + l32) * NN + rb * ROWS;
        #pragma unroll
        for (int o = 0; o < 2; o++) {
            const ulonglong2* pp = reinterpret_cast<const ulonglong2*>(rp + o * PB_Q);
            ulonglong2 v = pp[0];
            u64 accx = v.x, accy = v.y;
            #pragma unroll
            for (int j = 1; j < LANES; j++) {
                v = pp[j];
                accx = add2(accx, v.x);
                accy = add2(accy, v.y);
            }
            ulonglong2 out;
            out.x = mul2(accx, scy2);
            out.y = mul2(accy, scy2);
            *reinterpret_cast<ulonglong2*>(ybl + (2 * w + o) * 4) = out;
        }
    }

    // ---- final W ----
    {
        float* wb = w_out + (size_t)b * NN * NN + (size_t)r0 * NN + cseg;
        #pragma unroll
        for (int i = 0; i < TR; i++) {
            ulonglong2 v0, v1;
            v0.x = w2[i][0]; v0.y = w2[i][1];
            v1.x = w2[i][2]; v1.y = w2[i][3];
            reinterpret_cast<ulonglong2*>(wb + i * NN)[0] = v0;
            reinterpret_cast<ulonglong2*>(wb + i * NN)[1] = v1;
        }
    }
}

extern "C" void kernel_launch(void* const* d_in, const int* in_sizes, int n_in,
                              void* d_out, int out_size) {
    const float* x      = (const float*)d_in[0];
    const float* w_init = (const float*)d_in[1];
    const float* alpha  = (const float*)d_in[2];
    const float* eta    = (const float*)d_in[3];
    const int*   mask   = (const int*)d_in[4];

    float* w_out = (float*)d_out;
    float* y_out = (float*)d_out + (size_t)BB * NN * NN;

    static bool attr_set = false;
    if (!attr_set) {
        cudaFuncSetAttribute(bdh_scan_kernel,
                             cudaFuncAttributeMaxDynamicSharedMemorySize, SM_BYTES);
        attr_set = true;
    }

    dim3 grid(BB, RBLK);
    bdh_scan_kernel<<<grid, THREADS, SM_BYTES>>>(x, w_init, alpha, eta, mask,
                                                 w_out, y_out);
}

// round 16
// speedup vs baseline: 1.0503x; 1.0503x over previous
#include <cuda_runtime.h>

#define BB 32
#define TT 1024
#define NN 128
#define RBLK 4
#define ROWS 32
#define THREADS 128
#define TR 4
#define TC 8
#define LANES 16
#define CHUNK 32
#define NCHUNK (TT / CHUNK)

// pbuf in float4 units: [step][q][lane]; q stride 17, step stride 137
#define PB_Q    17
#define PB_STEP 137

// smem layout (float offsets)
#define SM_XS     0                                 // 3 x 4096 floats
#define SM_PBUF   (3 * CHUNK * NN)                  // 12288
#define SM_SCOEF  (SM_PBUF + CHUNK * PB_STEP * 4)   // +17536 = 29824 (16B aligned)
#define SM_CSCALE (SM_SCOEF + TT + 4)               // pad: sc4 over-read
#define SM_CFOLD  (SM_CSCALE + TT)
#define SM_APOW   (SM_CFOLD + NCHUNK)
#define SM_APOWI  (SM_APOW + CHUNK + 1)
#define SM_MBITS  (SM_APOWI + CHUNK + 1)
#define SM_MBAR   (((SM_MBITS + NCHUNK) + 3) & ~3)  // 16B aligned, 6 x u64
#define SM_FLOATS (SM_MBAR + 12)
#define SM_BYTES  (SM_FLOATS * 4)                   // ~128 KB

typedef unsigned long long u64;

// 16B-unit swizzle within each step's 32 units: kills the 2-way bank
// conflict of the lane*8 read pattern (quads become a permutation).
__host__ __device__ __forceinline__ int swz(int u) { return u ^ ((u >> 3) & 1); }

// ---------- packed f32x2 helpers ----------
__device__ __forceinline__ u64 pack2(float lo, float hi) {
    u64 r; asm("mov.b64 %0, {%1, %2};" : "=l"(r) : "f"(lo), "f"(hi)); return r;
}
__device__ __forceinline__ void unpack2(u64 v, float& lo, float& hi) {
    asm("mov.b64 {%0, %1}, %2;" : "=f"(lo), "=f"(hi) : "l"(v));
}
__device__ __forceinline__ u64 fma2(u64 a, u64 b, u64 c) {
    u64 d; asm("fma.rn.f32x2 %0, %1, %2, %3;" : "=l"(d) : "l"(a), "l"(b), "l"(c)); return d;
}
__device__ __forceinline__ u64 mul2(u64 a, u64 b) {
    u64 d; asm("mul.rn.f32x2 %0, %1, %2;" : "=l"(d) : "l"(a), "l"(b)); return d;
}
__device__ __forceinline__ u64 add2(u64 a, u64 b) {
    u64 d; asm("add.rn.f32x2 %0, %1, %2;" : "=l"(d) : "l"(a), "l"(b)); return d;
}

// ---------- mbarrier helpers ----------
__device__ __forceinline__ unsigned smem_u32(const void* p) {
    return (unsigned)__cvta_generic_to_shared(p);
}
__device__ __forceinline__ void mbar_init(unsigned a, unsigned cnt) {
    asm volatile("mbarrier.init.shared.b64 [%0], %1;" :: "r"(a), "r"(cnt) : "memory");
}
__device__ __forceinline__ void mbar_arrive(unsigned a) {
    asm volatile("mbarrier.arrive.shared.b64 _, [%0];" :: "r"(a) : "memory");
}
__device__ __forceinline__ void mbar_wait(unsigned a, unsigned parity) {
    unsigned done;
    do {
        asm volatile(
            "{\n\t.reg .pred p;\n\t"
            "mbarrier.try_wait.parity.acquire.cta.shared::cta.b64 p, [%1], %2, 0x989680;\n\t"
            "selp.b32 %0, 1, 0, p;\n\t}"
            : "=r"(done) : "r"(a), "r"(parity) : "memory");
    } while (!done);
}
// .noinc: completion arrive counts against the INIT count (proven in R12).
__device__ __forceinline__ void cpasync_mbar_arrive(unsigned a) {
    asm volatile("cp.async.mbarrier.arrive.noinc.shared::cta.b64 [%0];" :: "r"(a) : "memory");
}

// ---------- cp.async ----------
__device__ __forceinline__ void cpasync16(void* s, const void* g) {
    unsigned saddr = smem_u32(s);
    asm volatile("cp.async.cg.shared.global [%0], [%1], 16;" :: "r"(saddr), "l"(g));
}
// 4096 floats per chunk / 128 threads = 8 x 16B per thread, SWIZZLED dst
__device__ __forceinline__ void load_chunk(float* dst, const float* src, int tid) {
    #pragma unroll
    for (int i = 0; i < 8; i++) {
        const int U = tid + i * THREADS;     // global 16B-unit in chunk
        const int t = U >> 5;                // step
        const int u = U & 31;                // unit within step
        cpasync16(dst + t * NN + swz(u) * 4, src + U * 4);
    }
}

__global__ __launch_bounds__(THREADS, 1)
void bdh_scan_kernel(const float* __restrict__ x,
                     const float* __restrict__ w_init,
                     const float* __restrict__ alpha_p,
                     const float* __restrict__ eta_p,
                     const int*   __restrict__ mask,
                     float* __restrict__ w_out,
                     float* __restrict__ y_out)
{
    extern __shared__ float smem[];
    float*    xs     = smem + SM_XS;
    float4*   pbuf   = reinterpret_cast<float4*>(smem + SM_PBUF);
    float*    scoef  = smem + SM_SCOEF;
    float*    cscale = smem + SM_CSCALE;
    float*    cfold  = smem + SM_CFOLD;
    float*    apow   = smem + SM_APOW;
    float*    apowi  = smem + SM_APOWI;
    unsigned* mbits  = (unsigned*)(smem + SM_MBITS);
    const unsigned mb_base = smem_u32(smem + SM_MBAR);
    // full[i] at mb_base + i*8, empty[i] at mb_base + 24 + i*8

    const int b    = blockIdx.x;
    const int rb   = blockIdx.y;
    const int tid  = threadIdx.x;
    const int q    = tid / LANES;          // 0..7 row-group
    const int lane = tid % LANES;
    const int w    = tid >> 5;             // warp 0..3
    const int l32  = tid & 31;
    const int r0l  = q * TR;
    const int r0   = rb * ROWS + r0l;

    // swizzled x read offsets (floats)
    const int co0 = swz(2 * lane) * 4;          // xv units 2*lane
    const int co1 = swz(2 * lane + 1) * 4;      // xv unit  2*lane+1
    const int xro = swz(rb * 8 + q) * 4;        // xr unit (rows 4q..4q+3 of block)

    const float alpha = alpha_p[0];
    const float eta   = eta_p[0];
    const float inva  = 1.0f / alpha;

    const float* xb = x + (size_t)b * TT * NN;
    float* yb = y_out + (size_t)b * TT * NN;

    // ---- init mbarriers ----
    if (tid == 0) {
        #pragma unroll
        for (int i = 0; i < 3; i++) {
            mbar_init(mb_base + i * 8, THREADS);        // full
            mbar_init(mb_base + 24 + i * 8, THREADS);   // empty
        }
    }
    __syncthreads();
    mbar_arrive(mb_base + 24);
    mbar_arrive(mb_base + 32);
    mbar_arrive(mb_base + 40);

    // ---- prologue fills: buffers 0, 1 ----
    mbar_wait(mb_base + 24, 0);
    load_chunk(xs, xb, tid);
    cpasync_mbar_arrive(mb_base + 0);
    mbar_wait(mb_base + 32, 0);
    load_chunk(xs + CHUNK * NN, xb + CHUNK * NN, tid);
    cpasync_mbar_arrive(mb_base + 8);

    // ---- W tile: 4 rows x 8 cols = 16 packed f32x2 ----
    u64 w2[TR][4];
    {
        const float* wb = w_init + (size_t)b * NN * NN + (size_t)r0 * NN + lane * TC;
        #pragma unroll
        for (int i = 0; i < TR; i++) {
            const ulonglong2* ws = reinterpret_cast<const ulonglong2*>(wb + i * NN);
            ulonglong2 v0 = ws[0], v1 = ws[1];
            w2[i][0] = v0.x; w2[i][1] = v0.y; w2[i][2] = v1.x; w2[i][3] = v1.y;
        }
    }

    // ---- setup: mask bits + power tables ----
    for (int ckk = w; ckk < NCHUNK; ckk += 4) {
        int m = mask[(size_t)b * TT + ckk * 32 + l32];
        unsigned bits = __ballot_sync(0xffffffffu, m != 0);
        if (l32 == 0) mbits[ckk] = bits;
    }
    if (tid == 0) {
        float p = 1.0f, pi = 1.0f;
        #pragma unroll
        for (int k = 0; k <= CHUNK; k++) {
            apow[k] = p;  apowi[k] = pi;
            p *= alpha;   pi *= inva;
        }
    }
    __syncthreads();
    #pragma unroll
    for (int k = 0; k < 8; k++) {
        const int e = tid + k * THREADS;      // 0..1023
        const int ckk = e >> 5, tl = e & 31;
        const unsigned mb = mbits[ckk];
        const int cnt = __popc(mb & ((1u << tl) - 1u));
        cscale[e] = apow[cnt];
        scoef[e]  = ((mb >> tl) & 1u) ? (eta * apowi[cnt + 1]) : 0.0f;
    }
    if (tid < NCHUNK) cfold[tid] = apow[__popc(mbits[tid])];
    if (tid < 4) scoef[TT + tid] = 0.0f;      // sc4 over-read pad
    __syncthreads();   // tables visible; last block-wide sync

    float4* pbst = pbuf + q * PB_Q + lane;    // this thread's partial slot

    for (int ck = 0; ck < NCHUNK; ck++) {
        // prefetch ck+2 into buffer (ck+2)%3 once drained by all warps
        const int nk = ck + 2;
        if (nk < NCHUNK) {
            const int nb = nk % 3;
            mbar_wait(mb_base + 24 + nb * 8, (nk / 3) & 1);
            load_chunk(xs + nb * (CHUNK * NN), xb + (size_t)nk * CHUNK * NN, tid);
            cpasync_mbar_arrive(mb_base + nb * 8);
        }

        // wait this chunk's x (warp-independent)
        const int cb = ck % 3;
        mbar_wait(mb_base + cb * 8, (ck / 3) & 1);

        const float* xch = xs + cb * (CHUNK * NN);
        const float4* scp4 = reinterpret_cast<const float4*>(scoef + ck * CHUNK);

        // ---- software-pipelined, branch-free step loop ----
        ulonglong2 va = *reinterpret_cast<const ulonglong2*>(xch + co0);
        ulonglong2 vb = *reinterpret_cast<const ulonglong2*>(xch + co1);
        float4 xr = *reinterpret_cast<const float4*>(xch + xro);
        float4 sc4 = scp4[0];   // coefficients for steps 0..3

        #pragma unroll 16
        for (int tl = 0; tl < CHUNK; tl++) {
            const u64 xv0 = va.x, xv1 = va.y, xv2 = vb.x, xv3 = vb.y;
            const float4 xrc = xr;
            const float scc = (tl & 3) == 0 ? sc4.x :
                              (tl & 3) == 1 ? sc4.y :
                              (tl & 3) == 2 ? sc4.z : sc4.w;

            // prefetch next step (tl==31 over-reads pads; discarded)
            const float* xpn = xch + (tl + 1) * NN;
            va = *reinterpret_cast<const ulonglong2*>(xpn + co0);
            vb = *reinterpret_cast<const ulonglong2*>(xpn + co1);
            xr = *reinterpret_cast<const float4*>(xpn + xro);
            if ((tl & 3) == 3) sc4 = scp4[(tl >> 2) + 1];  // next 4-step batch

            // 4 independent dot chains (pre-update W)
            float p[TR];
            #pragma unroll
            for (int i = 0; i < TR; i++) {
                u64 a = mul2(w2[i][0], xv0);
                a = fma2(w2[i][1], xv1, a);
                a = fma2(w2[i][2], xv2, a);
                a = fma2(w2[i][3], xv3, a);
                float lo, hi; unpack2(a, lo, hi);
                p[i] = lo + hi;
            }
            pbst[tl * PB_STEP] = make_float4(p[0], p[1], p[2], p[3]);

            // branch-free masked update (scc == 0 on unmasked steps)
            const float g0f = scc * xrc.x, g1f = scc * xrc.y;
            const float g2f = scc * xrc.z, g3f = scc * xrc.w;
            const u64 g0 = pack2(g0f, g0f);
            const u64 g1 = pack2(g1f, g1f);
            const u64 g2 = pack2(g2f, g2f);
            const u64 g3 = pack2(g3f, g3f);
            w2[0][0] = fma2(g0, xv0, w2[0][0]);
            w2[0][1] = fma2(g0, xv1, w2[0][1]);
            w2[0][2] = fma2(g0, xv2, w2[0][2]);
            w2[0][3] = fma2(g0, xv3, w2[0][3]);
            w2[1][0] = fma2(g1, xv0, w2[1][0]);
            w2[1][1] = fma2(g1, xv1, w2[1][1]);
            w2[1][2] = fma2(g1, xv2, w2[1][2]);
            w2[1][3] = fma2(g1, xv3, w2[1][3]);
            w2[2][0] = fma2(g2, xv0, w2[2][0]);
            w2[2][1] = fma2(g2, xv1, w2[2][1]);
            w2[2][2] = fma2(g2, xv2, w2[2][2]);
            w2[2][3] = fma2(g2, xv3, w2[2][3]);
            w2[3][0] = fma2(g3, xv0, w2[3][0]);
            w2[3][1] = fma2(g3, xv1, w2[3][1]);
            w2[3][2] = fma2(g3, xv2, w2[3][2]);
            w2[3][3] = fma2(g3, xv3, w2[3][3]);
        }

        // unconditional decay fold
        {
            const float cf = cfold[ck];
            const u64 c2 = pack2(cf, cf);
            #pragma unroll
            for (int i = 0; i < TR; i++)
                #pragma unroll
                for (int k = 0; k < 4; k++) w2[i][k] = mul2(w2[i][k], c2);
        }

        // done reading xs[cb] -> release (128 arrivals total)
        mbar_arrive(mb_base + 24 + cb * 8);

        // warp-private reduce: rows 8w..8w+7 produced only by this warp
        __syncwarp();
        #pragma unroll
        for (int o = 0; o < 2; o++) {
            const int s  = l32;              // step in chunk
            const int qq = 2 * w + o;        // row-quad owned by this warp
            const ulonglong2* pp = reinterpret_cast<const ulonglong2*>(
                pbuf + s * PB_STEP + qq * PB_Q);
            ulonglong2 v0 = pp[0], v1 = pp[1], v2 = pp[2], v3 = pp[3];
            u64 ax0 = v0.x, ay0 = v0.y;
            u64 ax1 = v1.x, ay1 = v1.y;
            u64 ax2 = v2.x, ay2 = v2.y;
            u64 ax3 = v3.x, ay3 = v3.y;
            #pragma unroll
            for (int t = 4; t < LANES; t += 4) {
                ulonglong2 u0 = pp[t], u1 = pp[t + 1], u2 = pp[t + 2], u3 = pp[t + 3];
                ax0 = add2(ax0, u0.x); ay0 = add2(ay0, u0.y);
                ax1 = add2(ax1, u1.x); ay1 = add2(ay1, u1.y);
                ax2 = add2(ax2, u2.x); ay2 = add2(ay2, u2.y);
                ax3 = add2(ax3, u3.x); ay3 = add2(ay3, u3.y);
            }
            u64 accx = add2(add2(ax0, ax1), add2(ax2, ax3));
            u64 accy = add2(add2(ay0, ay1), add2(ay2, ay3));
            const float scy = cscale[ck * CHUNK + s];
            const u64 sc2 = pack2(scy, scy);
            ulonglong2 out;
            out.x = mul2(accx, sc2);
            out.y = mul2(accy, sc2);
            *reinterpret_cast<ulonglong2*>(
                yb + (size_t)(ck * CHUNK + s) * NN + rb * ROWS + qq * 4) = out;
        }
        __syncwarp();   // reduce reads done before next chunk's stores
    }

    // ---- final W ----
    {
        float* wb = w_out + (size_t)b * NN * NN + (size_t)r0 * NN + lane * TC;
        #pragma unroll
        for (int i = 0; i < TR; i++) {
            ulonglong2 v0, v1;
            v0.x = w2[i][0]; v0.y = w2[i][1];
            v1.x = w2[i][2]; v1.y = w2[i][3];
            reinterpret_cast<ulonglong2*>(wb + i * NN)[0] = v0;
            reinterpret_cast<ulonglong2*>(wb + i * NN)[1] = v1;
        }
    }
}

extern "C" void kernel_launch(void* const* d_in, const int* in_sizes, int n_in,
                              void* d_out, int out_size) {
    const float* x      = (const float*)d_in[0];
    const float* w_init = (const float*)d_in[1];
    const float* alpha  = (const float*)d_in[2];
    const float* eta    = (const float*)d_in[3];
    const int*   mask   = (const int*)d_in[4];

    float* w_out = (float*)d_out;
    float* y_out = (float*)d_out + (size_t)BB * NN * NN;

    static bool attr_set = false;
    if (!attr_set) {
        cudaFuncSetAttribute(bdh_scan_kernel,
                             cudaFuncAttributeMaxDynamicSharedMemorySize, SM_BYTES);
        attr_set = true;
    }

    dim3 grid(BB, RBLK);
    bdh_scan_kernel<<<grid, THREADS, SM_BYTES>>>(x, w_init, alpha, eta, mask,
                                                 w_out, y_out);
}